// round 2
// baseline (speedup 1.0000x reference)
#include <cuda_runtime.h>
#include <math.h>

#define N_ 307
#define T_ 12
#define B_ 32
#define H_ 64
#define E_ 10

constexpr long OFF_A    = 0;
constexpr long OFF_WG0  = OFF_A    + 94272;
constexpr long OFF_BG0  = OFF_WG0  + 307L*2*65*128;
constexpr long OFF_WU0  = OFF_BG0  + 307L*128;
constexpr long OFF_BU0  = OFF_WU0  + 307L*2*65*64;
constexpr long OFF_WG1  = OFF_BU0  + 307L*64;
constexpr long OFF_BG1  = OFF_WG1  + 307L*2*128*128;
constexpr long OFF_WU1  = OFF_BG1  + 307L*128;
constexpr long OFF_BU1  = OFF_WU1  + 307L*2*128*64;
constexpr long OFF_H    = OFF_BU1  + 307L*64;
constexpr long OFF_HS   = OFF_H    + 32L*307*64;
constexpr long OFF_CAT1 = OFF_HS   + 32L*12*307*64;
constexpr long OFF_SPR1 = OFF_CAT1 + 307L*32*128;
constexpr long OFF_CAT2 = OFF_SPR1 + 307L*32*128;
constexpr long OFF_SPR2 = OFF_CAT2 + 307L*32*128;
constexpr long OFF_ZR   = OFF_SPR2 + 307L*32*128;
constexpr long OFF_XB   = OFF_ZR   + 307L*32*128;
constexpr long OFF_K    = OFF_XB   + 9824L*12*64;
constexpr long OFF_V    = OFF_K    + 9824L*12*64;
constexpr long OFF_Q    = OFF_V    + 9824L*12*64;
constexpr long OFF_OB   = OFF_Q    + 9824L*64;
constexpr long OFF_LN1  = OFF_OB   + 9824L*64;
constexpr long OFF_F1   = OFF_LN1  + 9824L*64;
constexpr long OFF_F2   = OFF_F1   + 9824L*1024;
constexpr long SCRATCH_TOTAL = OFF_F2 + 9824L*64;

__device__ float SCRATCH[SCRATCH_TOTAL];

// A = softmax(relu(emb @ emb^T), axis=1)
__global__ void kA(const float* __restrict__ emb) {
    int n = blockIdx.x, tid = threadIdx.x;
    __shared__ float sc[N_];
    __shared__ float red[256];
    __shared__ float en[E_];
    if (tid < E_) en[tid] = emb[n*E_ + tid];
    __syncthreads();
    for (int m = tid; m < N_; m += 256) {
        float s = 0.f;
        #pragma unroll
        for (int e = 0; e < E_; e++) s += en[e]*emb[m*E_+e];
        sc[m] = fmaxf(s, 0.f);
    }
    __syncthreads();
    float mx = -1e30f;
    for (int m = tid; m < N_; m += 256) mx = fmaxf(mx, sc[m]);
    red[tid] = mx; __syncthreads();
    for (int s = 128; s > 0; s >>= 1) { if (tid < s) red[tid] = fmaxf(red[tid], red[tid+s]); __syncthreads(); }
    mx = red[0]; __syncthreads();
    float sum = 0.f;
    for (int m = tid; m < N_; m += 256) { float e = expf(sc[m]-mx); sc[m] = e; sum += e; }
    red[tid] = sum; __syncthreads();
    for (int s = 128; s > 0; s >>= 1) { if (tid < s) red[tid] += red[tid+s]; __syncthreads(); }
    float inv = 1.f/red[0];
    __syncthreads();
    for (int m = tid; m < N_; m += 256) SCRATCH[OFF_A + (long)n*N_ + m] = sc[m]*inv;
}

// per-node weight mix: dst[n,j] = sum_e emb[n,e] * w[e,j]
__global__ void kMix(const float* __restrict__ w, int J, long dstOff, const float* __restrict__ emb) {
    int n = blockIdx.y;
    __shared__ float en[E_];
    if (threadIdx.x < E_) en[threadIdx.x] = emb[n*E_ + threadIdx.x];
    __syncthreads();
    int j = blockIdx.x*256 + threadIdx.x;
    if (j >= J) return;
    float a = 0.f;
    #pragma unroll
    for (int e = 0; e < E_; e++) a += en[e]*w[(long)e*J + j];
    SCRATCH[dstOff + (long)n*J + j] = a;
}

__global__ void kZero(long off, long count) {
    long i = (long)blockIdx.x*256 + threadIdx.x;
    if (i < count) SCRATCH[off + i] = 0.f;
}

// generic tiled matmul: C = act(A@B + bias + res)
__global__ void __launch_bounds__(256) kMM(long aOff, int lda,
                    const float* __restrict__ Bx, long bOff, int ldb,
                    long cOff, int ldc, const float* __restrict__ bias,
                    long resOff, int ldres, int hasRes,
                    int M, int K, int Nc, int relu) {
    const float* A  = SCRATCH + aOff;
    const float* Bm = Bx ? Bx : (SCRATCH + bOff);
    float* Cm = SCRATCH + cOff;
    __shared__ float As[64][16];
    __shared__ float Bs[16][65];
    int tx = threadIdx.x & 15, ty = threadIdx.x >> 4;
    int row0 = blockIdx.y*64, col0 = blockIdx.x*64;
    float acc[4][4];
    #pragma unroll
    for (int i=0;i<4;i++)
        #pragma unroll
        for (int j=0;j<4;j++) acc[i][j]=0.f;
    for (int k0 = 0; k0 < K; k0 += 16) {
        for (int e = threadIdx.x; e < 64*16; e += 256) {
            int r = e >> 4, c = e & 15, gr = row0 + r, gc = k0 + c;
            As[r][c] = (gr < M && gc < K) ? A[(long)gr*lda + gc] : 0.f;
        }
        for (int e = threadIdx.x; e < 16*64; e += 256) {
            int r = e >> 6, c = e & 63, gr = k0 + r, gc = col0 + c;
            Bs[r][c] = (gr < K && gc < Nc) ? Bm[(long)gr*ldb + gc] : 0.f;
        }
        __syncthreads();
        #pragma unroll
        for (int kk = 0; kk < 16; kk++) {
            float a0=As[ty][kk], a1=As[ty+16][kk], a2=As[ty+32][kk], a3=As[ty+48][kk];
            float b0=Bs[kk][tx], b1=Bs[kk][tx+16], b2=Bs[kk][tx+32], b3=Bs[kk][tx+48];
            acc[0][0]+=a0*b0; acc[0][1]+=a0*b1; acc[0][2]+=a0*b2; acc[0][3]+=a0*b3;
            acc[1][0]+=a1*b0; acc[1][1]+=a1*b1; acc[1][2]+=a1*b2; acc[1][3]+=a1*b3;
            acc[2][0]+=a2*b0; acc[2][1]+=a2*b1; acc[2][2]+=a2*b2; acc[2][3]+=a2*b3;
            acc[3][0]+=a3*b0; acc[3][1]+=a3*b1; acc[3][2]+=a3*b2; acc[3][3]+=a3*b3;
        }
        __syncthreads();
    }
    #pragma unroll
    for (int i = 0; i < 4; i++) {
        int rr = row0 + ty + 16*i;
        if (rr >= M) continue;
        #pragma unroll
        for (int j = 0; j < 4; j++) {
            int cc = col0 + tx + 16*j;
            if (cc >= Nc) continue;
            float v = acc[i][j];
            if (bias)   v += bias[cc];
            if (hasRes) v += SCRATCH[resOff + (long)rr*ldres + cc];
            if (relu)   v = fmaxf(v, 0.f);
            Cm[(long)rr*ldc + cc] = v;
        }
    }
}

template<int CX>
__global__ void kCat1(const float* __restrict__ xsrc, int t) {
    const int C = CX + H_;
    int idx = blockIdx.x*256 + threadIdx.x;
    if (idx >= N_*B_*C) return;
    int c = idx % C, nb = idx / C, b = nb & 31, n = nb >> 5;
    float v;
    if (c < CX) {
        if (CX == 1) v = xsrc[((long)b*T_ + t)*N_ + n];
        else         v = SCRATCH[OFF_HS + (((long)b*T_ + t)*N_ + n)*H_ + c];
    } else v = SCRATCH[OFF_H + ((long)b*N_ + n)*H_ + (c - CX)];
    SCRATCH[OFF_CAT1 + idx] = v;
}

template<int CX>
__global__ void kCat2(const float* __restrict__ xsrc, int t) {
    const int C = CX + H_;
    int idx = blockIdx.x*256 + threadIdx.x;
    if (idx >= N_*B_*C) return;
    int c = idx % C, nb = idx / C, b = nb & 31, n = nb >> 5;
    float v;
    if (c < CX) {
        if (CX == 1) v = xsrc[((long)b*T_ + t)*N_ + n];
        else         v = SCRATCH[OFF_HS + (((long)b*T_ + t)*N_ + n)*H_ + c];
    } else {
        int j = c - CX;
        v = SCRATCH[OFF_ZR + ((long)n*B_ + b)*128 + j] * SCRATCH[OFF_H + ((long)b*N_ + n)*H_ + j];
    }
    SCRATCH[OFF_CAT2 + idx] = v;
}

// zr = sigmoid(cat1.W0 + spr1.W1 + Bg), 128 outputs
template<int C>
__global__ void __launch_bounds__(256) kGate(long wOff, long bOff) {
    int n = blockIdx.x, tid = threadIdx.x;
    __shared__ float c1[32*C];
    __shared__ float s1[32*C];
    long base = (long)n*(32*C);
    for (int i = tid; i < 32*C; i += 256) {
        c1[i] = SCRATCH[OFF_CAT1 + base + i];
        s1[i] = SCRATCH[OFF_SPR1 + base + i];
    }
    __syncthreads();
    int o = tid & 63, bg = tid >> 6;
    float acc0[8], acc1[8];
    #pragma unroll
    for (int i=0;i<8;i++){acc0[i]=0.f;acc1[i]=0.f;}
    const float* W = SCRATCH + wOff + (long)n*(2*C*128);
    for (int i = 0; i < C; i++) {
        float w00 = W[i*128 + o],     w01 = W[i*128 + o + 64];
        float w10 = W[(C+i)*128 + o], w11 = W[(C+i)*128 + o + 64];
        #pragma unroll
        for (int bb = 0; bb < 8; bb++) {
            float cv = c1[(bg*8+bb)*C + i], sv = s1[(bg*8+bb)*C + i];
            acc0[bb] += cv*w00 + sv*w10;
            acc1[bb] += cv*w01 + sv*w11;
        }
    }
    float bias0 = SCRATCH[bOff + (long)n*128 + o];
    float bias1 = SCRATCH[bOff + (long)n*128 + o + 64];
    #pragma unroll
    for (int bb = 0; bb < 8; bb++) {
        long zi = OFF_ZR + ((long)n*32 + bg*8+bb)*128 + o;
        SCRATCH[zi]      = 1.f/(1.f + expf(-(acc0[bb] + bias0)));
        SCRATCH[zi + 64] = 1.f/(1.f + expf(-(acc1[bb] + bias1)));
    }
}

// hc = tanh(cat2.W0 + spr2.W1 + Bu); h = r*h + (1-r)*hc
template<int C>
__global__ void __launch_bounds__(256) kUpd(long wOff, long bOff, int t, int writeHS) {
    int n = blockIdx.x, tid = threadIdx.x;
    __shared__ float c2[32*C];
    __shared__ float s2[32*C];
    long base = (long)n*(32*C);
    for (int i = tid; i < 32*C; i += 256) {
        c2[i] = SCRATCH[OFF_CAT2 + base + i];
        s2[i] = SCRATCH[OFF_SPR2 + base + i];
    }
    __syncthreads();
    int o = tid & 31, bg = tid >> 5;
    float acc0[4], acc1[4];
    #pragma unroll
    for (int i=0;i<4;i++){acc0[i]=0.f;acc1[i]=0.f;}
    const float* W = SCRATCH + wOff + (long)n*(2*C*64);
    for (int i = 0; i < C; i++) {
        float w00 = W[i*64 + o],     w01 = W[i*64 + o + 32];
        float w10 = W[(C+i)*64 + o], w11 = W[(C+i)*64 + o + 32];
        #pragma unroll
        for (int bb = 0; bb < 4; bb++) {
            float cv = c2[(bg*4+bb)*C + i], sv = s2[(bg*4+bb)*C + i];
            acc0[bb] += cv*w00 + sv*w10;
            acc1[bb] += cv*w01 + sv*w11;
        }
    }
    float bias0 = SCRATCH[bOff + (long)n*64 + o];
    float bias1 = SCRATCH[bOff + (long)n*64 + o + 32];
    #pragma unroll
    for (int bb = 0; bb < 4; bb++) {
        int b = bg*4 + bb;
        #pragma unroll
        for (int p = 0; p < 2; p++) {
            int oo = o + p*32;
            float hc = tanhf((p ? acc1[bb] : acc0[bb]) + (p ? bias1 : bias0));
            float r  = SCRATCH[OFF_ZR + ((long)n*32 + b)*128 + 64 + oo];
            long hidx = OFF_H + ((long)b*N_ + n)*H_ + oo;
            float hn = r*SCRATCH[hidx] + (1.f - r)*hc;
            SCRATCH[hidx] = hn;
            if (writeHS) SCRATCH[OFF_HS + (((long)b*T_ + t)*N_ + n)*H_ + oo] = hn;
        }
    }
}

// xb = src*mlp_w + mlp_b + pos_emb
__global__ void kX(const float* __restrict__ src, const float* __restrict__ mw,
                   const float* __restrict__ mb) {
    long idx = (long)blockIdx.x*256 + threadIdx.x;
    if (idx >= 9824L*12*64) return;
    int hh = (int)(idx & 63); long st = idx >> 6;
    int t = (int)(st % 12); long s = st / 12;
    int nn = (int)(s % N_); int b = (int)(s / N_);
    float j2 = (float)((hh >> 1)*2);
    float ang = (float)t * expf(-(j2/64.f)*9.210340371976184f);
    float pe = (hh & 1) ? cosf(ang) : sinf(ang);
    SCRATCH[OFF_XB + idx] = src[((long)b*T_ + t)*N_ + nn]*mw[hh] + mb[hh] + pe;
}

// attention for the single t=11 query row per (b,n)
__global__ void kAttn() {
    int s = blockIdx.x, tid = threadIdx.x;
    int w = tid >> 5, lane = tid & 31;
    __shared__ float qs[64];
    __shared__ float att[4][12];
    if (tid < 64) qs[tid] = SCRATCH[OFF_Q + (long)s*64 + tid];
    __syncthreads();
    if (lane < 12) {
        float sc = 0.f;
        #pragma unroll
        for (int d = 0; d < 16; d++)
            sc += qs[w*16+d] * SCRATCH[OFF_K + (long)s*768 + lane*64 + w*16 + d];
        att[w][lane] = sc * 0.25f;
    }
    __syncwarp();
    float loc[12], mx = -1e30f, sum = 0.f;
    #pragma unroll
    for (int t = 0; t < 12; t++) { loc[t] = att[w][t]; mx = fmaxf(mx, loc[t]); }
    #pragma unroll
    for (int t = 0; t < 12; t++) { loc[t] = expf(loc[t]-mx); sum += loc[t]; }
    float inv = 1.f/sum;
    __syncwarp();
    if (lane < 16) {
        float acc = 0.f;
        #pragma unroll
        for (int t = 0; t < 12; t++)
            acc += loc[t]*inv * SCRATCH[OFF_V + (long)s*768 + t*64 + w*16 + lane];
        SCRATCH[OFF_OB + (long)s*64 + w*16 + lane] = acc;
    }
}

__global__ void kLN(long inOff, long outOff, const float* __restrict__ g, const float* __restrict__ b) {
    int row = blockIdx.x, tid = threadIdx.x;
    __shared__ float red[64];
    float v = SCRATCH[inOff + (long)row*64 + tid];
    red[tid] = v; __syncthreads();
    for (int s = 32; s > 0; s >>= 1) { if (tid < s) red[tid] += red[tid+s]; __syncthreads(); }
    float m = red[0]/64.f; __syncthreads();
    float d = v - m;
    red[tid] = d*d; __syncthreads();
    for (int s = 32; s > 0; s >>= 1) { if (tid < s) red[tid] += red[tid+s]; __syncthreads(); }
    float var = red[0]/64.f;
    SCRATCH[outOff + (long)row*64 + tid] = d*rsqrtf(var + 1e-5f)*g[tid] + b[tid];
}

__global__ void kOut(float* __restrict__ out, const float* __restrict__ ws, const float* __restrict__ wt,
                     const float* __restrict__ cw, const float* __restrict__ cb) {
    int s = blockIdx.x, tid = threadIdx.x;
    int n = s % N_, b = s / N_;
    __shared__ float comb[64];
    comb[tid] = SCRATCH[OFF_H + (long)s*64 + tid]*ws[n*64+tid]
              + SCRATCH[OFF_OB + (long)s*64 + tid]*wt[n*64+tid];
    __syncthreads();
    if (tid < 12) {
        float acc = cb[tid];
        #pragma unroll
        for (int h = 0; h < 64; h++) acc += comb[h]*cw[tid*64+h];
        out[((long)b*12 + tid)*N_ + n] = acc;
    }
}

extern "C" void kernel_launch(void* const* d_in, const int* in_sizes, int n_in,
                              void* d_out, int out_size) {
    const float* source  = (const float*)d_in[0];
    const float* emb     = (const float*)d_in[1];
    const float* gate_w0 = (const float*)d_in[2];
    const float* gate_b0 = (const float*)d_in[3];
    const float* upd_w0  = (const float*)d_in[4];
    const float* upd_b0  = (const float*)d_in[5];
    const float* gate_w1 = (const float*)d_in[6];
    const float* gate_b1 = (const float*)d_in[7];
    const float* upd_w1  = (const float*)d_in[8];
    const float* upd_b1  = (const float*)d_in[9];
    const float* mlp_w   = (const float*)d_in[10];
    const float* mlp_b   = (const float*)d_in[11];
    const float* wq = (const float*)d_in[12];  const float* bq = (const float*)d_in[13];
    const float* wk = (const float*)d_in[14];  const float* bk = (const float*)d_in[15];
    const float* wv = (const float*)d_in[16];  const float* bv = (const float*)d_in[17];
    const float* wo = (const float*)d_in[18];  const float* bo = (const float*)d_in[19];
    const float* fw1 = (const float*)d_in[20]; const float* fb1 = (const float*)d_in[21];
    const float* fw2 = (const float*)d_in[22]; const float* fb2 = (const float*)d_in[23];
    const float* l1g = (const float*)d_in[24]; const float* l1b = (const float*)d_in[25];
    const float* l2g = (const float*)d_in[26]; const float* l2b = (const float*)d_in[27];
    const float* ws  = (const float*)d_in[28]; const float* wt  = (const float*)d_in[29];
    const float* cw  = (const float*)d_in[30]; const float* cb  = (const float*)d_in[31];
    float* out = (float*)d_out;

    kA<<<N_, 256>>>(emb);
    kMix<<<dim3(65,N_),256>>>(gate_w0, 2*65*128, OFF_WG0, emb);
    kMix<<<dim3(1,N_),256>>>(gate_b0, 128, OFF_BG0, emb);
    kMix<<<dim3(33,N_),256>>>(upd_w0, 2*65*64, OFF_WU0, emb);
    kMix<<<dim3(1,N_),256>>>(upd_b0, 64, OFF_BU0, emb);
    kMix<<<dim3(128,N_),256>>>(gate_w1, 2*128*128, OFF_WG1, emb);
    kMix<<<dim3(1,N_),256>>>(gate_b1, 128, OFF_BG1, emb);
    kMix<<<dim3(64,N_),256>>>(upd_w1, 2*128*64, OFF_WU1, emb);
    kMix<<<dim3(1,N_),256>>>(upd_b1, 64, OFF_BU1, emb);

    // ---- GRU layer 0 (C = 65) ----
    kZero<<<2456,256>>>(OFF_H, 32L*307*64);
    for (int t = 0; t < T_; t++) {
        kCat1<1><<<2495,256>>>(source, t);
        kMM<<<dim3(33,5),256>>>(OFF_A,307, nullptr,OFF_CAT1,2080, OFF_SPR1,2080, nullptr,0,0,0, 307,307,2080,0);
        kGate<65><<<N_,256>>>(OFF_WG0, OFF_BG0);
        kCat2<1><<<2495,256>>>(source, t);
        kMM<<<dim3(33,5),256>>>(OFF_A,307, nullptr,OFF_CAT2,2080, OFF_SPR2,2080, nullptr,0,0,0, 307,307,2080,0);
        kUpd<65><<<N_,256>>>(OFF_WU0, OFF_BU0, t, 1);
    }
    // ---- GRU layer 1 (C = 128) ----
    kZero<<<2456,256>>>(OFF_H, 32L*307*64);
    for (int t = 0; t < T_; t++) {
        kCat1<64><<<4912,256>>>(source, t);
        kMM<<<dim3(64,5),256>>>(OFF_A,307, nullptr,OFF_CAT1,4096, OFF_SPR1,4096, nullptr,0,0,0, 307,307,4096,0);
        kGate<128><<<N_,256>>>(OFF_WG1, OFF_BG1);
        kCat2<64><<<4912,256>>>(source, t);
        kMM<<<dim3(64,5),256>>>(OFF_A,307, nullptr,OFF_CAT2,4096, OFF_SPR2,4096, nullptr,0,0,0, 307,307,4096,0);
        kUpd<128><<<N_,256>>>(OFF_WU1, OFF_BU1, t, 0);
    }

    // ---- transformer branch (only t=11 survives) ----
    kX<<<29472,256>>>(source, mlp_w, mlp_b);
    kMM<<<dim3(1,1842),256>>>(OFF_XB,64, wk,0,64, OFF_K,64, bk, 0,0,0, 117888,64,64,0);
    kMM<<<dim3(1,1842),256>>>(OFF_XB,64, wv,0,64, OFF_V,64, bv, 0,0,0, 117888,64,64,0);
    kMM<<<dim3(1,154),256>>>(OFF_XB + 11*64,768, wq,0,64, OFF_Q,64, bq, 0,0,0, 9824,64,64,0);
    kAttn<<<9824,128>>>();
    kMM<<<dim3(1,154),256>>>(OFF_OB,64, wo,0,64, OFF_Q,64, bo, OFF_XB + 11*64,768,1, 9824,64,64,0);
    kLN<<<9824,64>>>(OFF_Q, OFF_LN1, l1g, l1b);
    kMM<<<dim3(16,154),256>>>(OFF_LN1,64, fw1,0,1024, OFF_F1,1024, fb1, 0,0,0, 9824,64,1024,1);
    kMM<<<dim3(1,154),256>>>(OFF_F1,1024, fw2,0,64, OFF_F2,64, fb2, OFF_LN1,64,1, 9824,1024,64,0);
    kLN<<<9824,64>>>(OFF_F2, OFF_OB, l2g, l2b);

    kOut<<<9824,64>>>(out, ws, wt, cw, cb);
}

// round 4
// speedup vs baseline: 1.0167x; 1.0167x over previous
#include <cuda_runtime.h>
#include <math.h>

#define N_ 307
#define T_ 12
#define B_ 32
#define H_ 64
#define E_ 10

typedef unsigned long long ull;

constexpr long OFF_A    = 0;
constexpr long OFF_WG0  = OFF_A    + 94272;
constexpr long OFF_BG0  = OFF_WG0  + 307L*2*65*128;
constexpr long OFF_WU0  = OFF_BG0  + 307L*128;
constexpr long OFF_BU0  = OFF_WU0  + 307L*2*65*64;
constexpr long OFF_WG1  = OFF_BU0  + 307L*64;
constexpr long OFF_BG1  = OFF_WG1  + 307L*2*128*128;
constexpr long OFF_WU1  = OFF_BG1  + 307L*128;
constexpr long OFF_BU1  = OFF_WU1  + 307L*2*128*64;
constexpr long OFF_H    = OFF_BU1  + 307L*64;
constexpr long OFF_HS   = OFF_H    + 32L*307*64;
constexpr long OFF_SPR1 = OFF_HS   + 32L*12*307*64;
constexpr long OFF_SPR2 = OFF_SPR1 + 307L*32*128;
constexpr long OFF_ZR   = OFF_SPR2 + 307L*32*128;
constexpr long OFF_XB   = OFF_ZR   + 307L*32*128;
constexpr long OFF_K    = OFF_XB   + 9824L*12*64;
constexpr long OFF_V    = OFF_K    + 9824L*12*64;
constexpr long OFF_Q    = OFF_V    + 9824L*12*64;
constexpr long OFF_OB   = OFF_Q    + 9824L*64;
constexpr long OFF_LN1  = OFF_OB   + 9824L*64;
constexpr long OFF_F1   = OFF_LN1  + 9824L*64;
constexpr long OFF_F2   = OFF_F1   + 9824L*1024;
constexpr long SCRATCH_TOTAL = OFF_F2 + 9824L*64;

__device__ float SCRATCH[SCRATCH_TOTAL];

// A = softmax(relu(emb @ emb^T), axis=1)
__global__ void kA(const float* __restrict__ emb) {
    int n = blockIdx.x, tid = threadIdx.x;
    __shared__ float sc[N_];
    __shared__ float red[256];
    __shared__ float en[E_];
    if (tid < E_) en[tid] = emb[n*E_ + tid];
    __syncthreads();
    for (int m = tid; m < N_; m += 256) {
        float s = 0.f;
        #pragma unroll
        for (int e = 0; e < E_; e++) s += en[e]*emb[m*E_+e];
        sc[m] = fmaxf(s, 0.f);
    }
    __syncthreads();
    float mx = -1e30f;
    for (int m = tid; m < N_; m += 256) mx = fmaxf(mx, sc[m]);
    red[tid] = mx; __syncthreads();
    for (int s = 128; s > 0; s >>= 1) { if (tid < s) red[tid] = fmaxf(red[tid], red[tid+s]); __syncthreads(); }
    mx = red[0]; __syncthreads();
    float sum = 0.f;
    for (int m = tid; m < N_; m += 256) { float e = expf(sc[m]-mx); sc[m] = e; sum += e; }
    red[tid] = sum; __syncthreads();
    for (int s = 128; s > 0; s >>= 1) { if (tid < s) red[tid] += red[tid+s]; __syncthreads(); }
    float inv = 1.f/red[0];
    __syncthreads();
    for (int m = tid; m < N_; m += 256) SCRATCH[OFF_A + (long)n*N_ + m] = sc[m]*inv;
}

// plain per-node mix (biases): dst[n,j] = sum_e emb[n,e]*w[e,j]
__global__ void kMix(const float* __restrict__ w, int J, long dstOff, const float* __restrict__ emb) {
    int n = blockIdx.y;
    __shared__ float en[E_];
    if (threadIdx.x < E_) en[threadIdx.x] = emb[n*E_ + threadIdx.x];
    __syncthreads();
    int j = blockIdx.x*256 + threadIdx.x;
    if (j >= J) return;
    float a = 0.f;
    #pragma unroll
    for (int e = 0; e < E_; e++) a += en[e]*w[(long)e*J + j];
    SCRATCH[dstOff + (long)n*J + j] = a;
}

// packed per-node weight mix: w[e][k][i][o] -> dst[n][(i*O+o)*2 + k]  (pairs over support k)
__global__ void kMixPack(const float* __restrict__ w, int CO, long dstOff, const float* __restrict__ emb) {
    int n = blockIdx.y;
    __shared__ float en[E_];
    if (threadIdx.x < E_) en[threadIdx.x] = emb[n*E_ + threadIdx.x];
    __syncthreads();
    int j = blockIdx.x*256 + threadIdx.x;
    if (j >= 2*CO) return;
    float a = 0.f;
    #pragma unroll
    for (int e = 0; e < E_; e++) a += en[e]*w[(long)e*2*CO + j];
    int k = j / CO, r = j - k*CO;
    SCRATCH[dstOff + (long)n*2*CO + (long)r*2 + k] = a;
}

__global__ void kZero(long off, long count) {
    long i = (long)blockIdx.x*256 + threadIdx.x;
    if (i < count) SCRATCH[off + i] = 0.f;
}

// ---- B-operand gather for the spread GEMMs ----
template<int MODE>
__device__ __forceinline__ float gatherB(const float* __restrict__ Bx, int ldb,
                                         const float* __restrict__ src, int t,
                                         int m, int gc) {
    if (MODE == 0) return Bx[(long)m*ldb + gc];
    if (MODE == 1) {                      // L0 spr1: cat = [x | h], cols b*65+c
        int b = gc/65, c = gc - b*65;
        if (c == 0) return src[((long)b*T_+t)*N_ + m];
        return SCRATCH[OFF_H + ((long)b*N_+m)*H_ + (c-1)];
    }
    if (MODE == 2) {                      // L0 spr2: cat = [x | z*h]
        int b = gc/65, c = gc - b*65;
        if (c == 0) return src[((long)b*T_+t)*N_ + m];
        int j = c-1;
        return SCRATCH[OFF_ZR + ((long)m*B_+b)*128 + j] *
               SCRATCH[OFF_H + ((long)b*N_+m)*H_ + j];
    }
    if (MODE == 3) {                      // L1 spr1: [hs(2048) | h(2048)]
        if (gc < 2048) {
            int b = gc>>6, c = gc&63;
            return SCRATCH[OFF_HS + (((long)b*T_+t)*N_+m)*H_ + c];
        }
        int g = gc-2048; int b = g>>6, c = g&63;
        return SCRATCH[OFF_H + ((long)b*N_+m)*H_ + c];
    }
    // MODE 4: L1 spr2: z*h only (2048 cols)
    int b = gc>>6, c = gc&63;
    return SCRATCH[OFF_ZR + ((long)m*B_+b)*128 + c] *
           SCRATCH[OFF_H + ((long)b*N_+m)*H_ + c];
}

// tiled matmul with f32x2 FMA: C = act(A@B + bias + res). Tile 64 x NT.
template<int MODE, int NT>
__global__ void __launch_bounds__(256) kMM(long aOff, int lda,
        const float* __restrict__ Bx, int ldb,
        long cOff, int ldc, const float* __restrict__ bias,
        long resOff, int ldres, int hasRes,
        int M, int K, int Nc, int relu,
        const float* __restrict__ src, int t) {
    const int P = NT/32;
    const float* A = SCRATCH + aOff;
    float* Cm = SCRATCH + cOff;
    __shared__ float As[64][16];
    __shared__ float Bs[16][NT+2];
    int tx = threadIdx.x & 15, ty = threadIdx.x >> 4;
    int row0 = blockIdx.y*64, col0 = blockIdx.x*NT;
    ull acc[4][P];
    #pragma unroll
    for (int i=0;i<4;i++)
        #pragma unroll
        for (int p=0;p<P;p++) acc[i][p] = 0ull;
    for (int k0 = 0; k0 < K; k0 += 16) {
        for (int e = threadIdx.x; e < 64*16; e += 256) {
            int r = e >> 4, c = e & 15, gr = row0 + r, gc = k0 + c;
            As[r][c] = (gr < M && gc < K) ? A[(long)gr*lda + gc] : 0.f;
        }
        for (int e = threadIdx.x; e < 16*NT; e += 256) {
            int r = e / NT, c = e - (e/NT)*NT;
            int gr = k0 + r, gc = col0 + c;
            Bs[r][c] = (gr < K && gc < Nc) ? gatherB<MODE>(Bx, ldb, src, t, gr, gc) : 0.f;
        }
        __syncthreads();
        #pragma unroll
        for (int kk = 0; kk < 16; kk++) {
            ull bv[P];
            #pragma unroll
            for (int p=0;p<P;p++) bv[p] = *(const ull*)&Bs[kk][32*p + 2*tx];
            #pragma unroll
            for (int i=0;i<4;i++) {
                float a = As[ty + 16*i][kk];
                ull aa;
                asm("mov.b64 %0, {%1, %1};" : "=l"(aa) : "f"(a));
                #pragma unroll
                for (int p=0;p<P;p++)
                    asm("fma.rn.f32x2 %0, %1, %2, %0;" : "+l"(acc[i][p]) : "l"(aa), "l"(bv[p]));
            }
        }
        __syncthreads();
    }
    #pragma unroll
    for (int i=0;i<4;i++) {
        int rr = row0 + ty + 16*i;
        if (rr >= M) continue;
        #pragma unroll
        for (int p=0;p<P;p++) {
            float2 v = *(float2*)&acc[i][p];
            int cc = col0 + 32*p + 2*tx;
            #pragma unroll
            for (int q=0;q<2;q++) {
                int c2 = cc + q;
                if (c2 >= Nc) continue;
                float val = q ? v.y : v.x;
                if (bias)   val += bias[c2];
                if (hasRes) val += SCRATCH[resOff + (long)rr*ldres + c2];
                if (relu)   val = fmaxf(val, 0.f);
                Cm[(long)rr*ldc + c2] = val;
            }
        }
    }
}

// gate: zr = sigmoid(cat.Wc + spr.Ws + Bg)  -- packed (cat,spr) x (Wc,Ws) f32x2 pairs
template<int C, int L>
__global__ void __launch_bounds__(256) kGate(long wOff, long bOff, const float* __restrict__ src, int t) {
    int n = blockIdx.x, tid = threadIdx.x;
    __shared__ float2 cs[32*C];
    for (int idx = tid; idx < 32*C; idx += 256) {
        int b = idx / C, c = idx - (idx/C)*C;
        float cv, sv;
        if (L == 0) {
            cv = (c == 0) ? src[((long)b*T_+t)*N_ + n]
                          : SCRATCH[OFF_H + ((long)b*N_+n)*H_ + (c-1)];
            sv = SCRATCH[OFF_SPR1 + (long)n*2080 + b*65 + c];
        } else {
            if (c < 64) {
                cv = SCRATCH[OFF_HS + (((long)b*T_+t)*N_+n)*H_ + c];
                sv = SCRATCH[OFF_SPR1 + (long)n*4096 + b*64 + c];
            } else {
                cv = SCRATCH[OFF_H + ((long)b*N_+n)*H_ + (c-64)];
                sv = SCRATCH[OFF_SPR1 + (long)n*4096 + 2048 + b*64 + (c-64)];
            }
        }
        cs[idx] = make_float2(cv, sv);
    }
    __syncthreads();
    int o = tid & 63, bg = tid >> 6;
    ull acc0[8], acc1[8];
    #pragma unroll
    for (int i=0;i<8;i++){acc0[i]=0ull;acc1[i]=0ull;}
    const float2* Wp = (const float2*)(SCRATCH + wOff + (long)n*(2*C*128));
    const float2* csb = cs + bg*8*C;
    for (int i = 0; i < C; i++) {
        ull wa = *(const ull*)(Wp + i*128 + o);
        ull wb = *(const ull*)(Wp + i*128 + o + 64);
        #pragma unroll
        for (int bb = 0; bb < 8; bb++) {
            ull cp = *(const ull*)(csb + bb*C + i);
            asm("fma.rn.f32x2 %0, %1, %2, %0;" : "+l"(acc0[bb]) : "l"(cp), "l"(wa));
            asm("fma.rn.f32x2 %0, %1, %2, %0;" : "+l"(acc1[bb]) : "l"(cp), "l"(wb));
        }
    }
    float bias0 = SCRATCH[bOff + (long)n*128 + o];
    float bias1 = SCRATCH[bOff + (long)n*128 + o + 64];
    #pragma unroll
    for (int bb = 0; bb < 8; bb++) {
        float2 a0 = *(float2*)&acc0[bb];
        float2 a1 = *(float2*)&acc1[bb];
        long zi = OFF_ZR + ((long)n*32 + bg*8+bb)*128 + o;
        SCRATCH[zi]      = 1.f/(1.f + expf(-(a0.x + a0.y + bias0)));
        SCRATCH[zi + 64] = 1.f/(1.f + expf(-(a1.x + a1.y + bias1)));
    }
}

// update: hc = tanh(cat2.Wc + spr2.Ws + Bu); h = r*h + (1-r)*hc
template<int C, int L>
__global__ void __launch_bounds__(256) kUpd(long wOff, long bOff, const float* __restrict__ src,
                                            int t, int writeHS) {
    int n = blockIdx.x, tid = threadIdx.x;
    __shared__ float2 cs[32*C];
    for (int idx = tid; idx < 32*C; idx += 256) {
        int b = idx / C, c = idx - (idx/C)*C;
        float cv, sv;
        if (L == 0) {
            if (c == 0) cv = src[((long)b*T_+t)*N_ + n];
            else {
                int j = c-1;
                cv = SCRATCH[OFF_ZR + ((long)n*32+b)*128 + j] *
                     SCRATCH[OFF_H + ((long)b*N_+n)*H_ + j];
            }
            sv = SCRATCH[OFF_SPR2 + (long)n*2080 + b*65 + c];
        } else {
            if (c < 64) {
                cv = SCRATCH[OFF_HS + (((long)b*T_+t)*N_+n)*H_ + c];
                sv = SCRATCH[OFF_SPR1 + (long)n*4096 + b*64 + c];
            } else {
                int j = c-64;
                cv = SCRATCH[OFF_ZR + ((long)n*32+b)*128 + j] *
                     SCRATCH[OFF_H + ((long)b*N_+n)*H_ + j];
                sv = SCRATCH[OFF_SPR2 + (long)n*2048 + b*64 + j];
            }
        }
        cs[idx] = make_float2(cv, sv);
    }
    __syncthreads();
    int o = tid & 31, bg = tid >> 5;  // 8 groups x 4 batches
    ull acc0[4], acc1[4];
    #pragma unroll
    for (int i=0;i<4;i++){acc0[i]=0ull;acc1[i]=0ull;}
    const float2* Wp = (const float2*)(SCRATCH + wOff + (long)n*(2*C*64));
    const float2* csb = cs + bg*4*C;
    for (int i = 0; i < C; i++) {
        ull wa = *(const ull*)(Wp + i*64 + o);
        ull wb = *(const ull*)(Wp + i*64 + o + 32);
        #pragma unroll
        for (int bb = 0; bb < 4; bb++) {
            ull cp = *(const ull*)(csb + bb*C + i);
            asm("fma.rn.f32x2 %0, %1, %2, %0;" : "+l"(acc0[bb]) : "l"(cp), "l"(wa));
            asm("fma.rn.f32x2 %0, %1, %2, %0;" : "+l"(acc1[bb]) : "l"(cp), "l"(wb));
        }
    }
    float bias0 = SCRATCH[bOff + (long)n*64 + o];
    float bias1 = SCRATCH[bOff + (long)n*64 + o + 32];
    #pragma unroll
    for (int bb = 0; bb < 4; bb++) {
        int b = bg*4 + bb;
        float2 a0 = *(float2*)&acc0[bb];
        float2 a1 = *(float2*)&acc1[bb];
        #pragma unroll
        for (int p = 0; p < 2; p++) {
            int oo = o + p*32;
            float hc = tanhf((p ? (a1.x+a1.y+bias1) : (a0.x+a0.y+bias0)));
            float r  = SCRATCH[OFF_ZR + ((long)n*32 + b)*128 + 64 + oo];
            long hidx = OFF_H + ((long)b*N_ + n)*H_ + oo;
            float hn = r*SCRATCH[hidx] + (1.f - r)*hc;
            SCRATCH[hidx] = hn;
            if (writeHS) SCRATCH[OFF_HS + (((long)b*T_ + t)*N_ + n)*H_ + oo] = hn;
        }
    }
}

// xb = src*mlp_w + mlp_b + pos_emb
__global__ void kX(const float* __restrict__ src, const float* __restrict__ mw,
                   const float* __restrict__ mb) {
    long idx = (long)blockIdx.x*256 + threadIdx.x;
    if (idx >= 9824L*12*64) return;
    int hh = (int)(idx & 63); long st = idx >> 6;
    int t = (int)(st % 12); long s = st / 12;
    int nn = (int)(s % N_); int b = (int)(s / N_);
    float j2 = (float)((hh >> 1)*2);
    float ang = (float)t * expf(-(j2/64.f)*9.210340371976184f);
    float pe = (hh & 1) ? cosf(ang) : sinf(ang);
    SCRATCH[OFF_XB + idx] = src[((long)b*T_ + t)*N_ + nn]*mw[hh] + mb[hh] + pe;
}

// attention for the single t=11 query row per (b,n)
__global__ void kAttn() {
    int s = blockIdx.x, tid = threadIdx.x;
    int w = tid >> 5, lane = tid & 31;
    __shared__ float qs[64];
    __shared__ float att[4][12];
    if (tid < 64) qs[tid] = SCRATCH[OFF_Q + (long)s*64 + tid];
    __syncthreads();
    if (lane < 12) {
        float sc = 0.f;
        #pragma unroll
        for (int d = 0; d < 16; d++)
            sc += qs[w*16+d] * SCRATCH[OFF_K + (long)s*768 + lane*64 + w*16 + d];
        att[w][lane] = sc * 0.25f;
    }
    __syncwarp();
    float loc[12], mx = -1e30f, sum = 0.f;
    #pragma unroll
    for (int t = 0; t < 12; t++) { loc[t] = att[w][t]; mx = fmaxf(mx, loc[t]); }
    #pragma unroll
    for (int t = 0; t < 12; t++) { loc[t] = expf(loc[t]-mx); sum += loc[t]; }
    float inv = 1.f/sum;
    __syncwarp();
    if (lane < 16) {
        float acc = 0.f;
        #pragma unroll
        for (int t = 0; t < 12; t++)
            acc += loc[t]*inv * SCRATCH[OFF_V + (long)s*768 + t*64 + w*16 + lane];
        SCRATCH[OFF_OB + (long)s*64 + w*16 + lane] = acc;
    }
}

__global__ void kLN(long inOff, long outOff, const float* __restrict__ g, const float* __restrict__ b) {
    int row = blockIdx.x, tid = threadIdx.x;
    __shared__ float red[64];
    float v = SCRATCH[inOff + (long)row*64 + tid];
    red[tid] = v; __syncthreads();
    for (int s = 32; s > 0; s >>= 1) { if (tid < s) red[tid] += red[tid+s]; __syncthreads(); }
    float m = red[0]/64.f; __syncthreads();
    float d = v - m;
    red[tid] = d*d; __syncthreads();
    for (int s = 32; s > 0; s >>= 1) { if (tid < s) red[tid] += red[tid+s]; __syncthreads(); }
    float var = red[0]/64.f;
    SCRATCH[outOff + (long)row*64 + tid] = d*rsqrtf(var + 1e-5f)*g[tid] + b[tid];
}

__global__ void kOut(float* __restrict__ out, const float* __restrict__ ws, const float* __restrict__ wt,
                     const float* __restrict__ cw, const float* __restrict__ cb) {
    int s = blockIdx.x, tid = threadIdx.x;
    int n = s % N_, b = s / N_;
    __shared__ float comb[64];
    comb[tid] = SCRATCH[OFF_H + (long)s*64 + tid]*ws[n*64+tid]
              + SCRATCH[OFF_OB + (long)s*64 + tid]*wt[n*64+tid];
    __syncthreads();
    if (tid < 12) {
        float acc = cb[tid];
        #pragma unroll
        for (int h = 0; h < 64; h++) acc += comb[h]*cw[tid*64+h];
        out[((long)b*12 + tid)*N_ + n] = acc;
    }
}

extern "C" void kernel_launch(void* const* d_in, const int* in_sizes, int n_in,
                              void* d_out, int out_size) {
    const float* source  = (const float*)d_in[0];
    const float* emb     = (const float*)d_in[1];
    const float* gate_w0 = (const float*)d_in[2];
    const float* gate_b0 = (const float*)d_in[3];
    const float* upd_w0  = (const float*)d_in[4];
    const float* upd_b0  = (const float*)d_in[5];
    const float* gate_w1 = (const float*)d_in[6];
    const float* gate_b1 = (const float*)d_in[7];
    const float* upd_w1  = (const float*)d_in[8];
    const float* upd_b1  = (const float*)d_in[9];
    const float* mlp_w   = (const float*)d_in[10];
    const float* mlp_b   = (const float*)d_in[11];
    const float* wq = (const float*)d_in[12];  const float* bq = (const float*)d_in[13];
    const float* wk = (const float*)d_in[14];  const float* bk = (const float*)d_in[15];
    const float* wv = (const float*)d_in[16];  const float* bv = (const float*)d_in[17];
    const float* wo = (const float*)d_in[18];  const float* bo = (const float*)d_in[19];
    const float* fw1 = (const float*)d_in[20]; const float* fb1 = (const float*)d_in[21];
    const float* fw2 = (const float*)d_in[22]; const float* fb2 = (const float*)d_in[23];
    const float* l1g = (const float*)d_in[24]; const float* l1b = (const float*)d_in[25];
    const float* l2g = (const float*)d_in[26]; const float* l2b = (const float*)d_in[27];
    const float* ws  = (const float*)d_in[28]; const float* wt  = (const float*)d_in[29];
    const float* cw  = (const float*)d_in[30]; const float* cb  = (const float*)d_in[31];
    float* out = (float*)d_out;

    kA<<<N_, 256>>>(emb);
    kMixPack<<<dim3(65,N_),256>>>(gate_w0, 65*128, OFF_WG0, emb);
    kMix<<<dim3(1,N_),256>>>(gate_b0, 128, OFF_BG0, emb);
    kMixPack<<<dim3(33,N_),256>>>(upd_w0, 65*64, OFF_WU0, emb);
    kMix<<<dim3(1,N_),256>>>(upd_b0, 64, OFF_BU0, emb);
    kMixPack<<<dim3(128,N_),256>>>(gate_w1, 128*128, OFF_WG1, emb);
    kMix<<<dim3(1,N_),256>>>(gate_b1, 128, OFF_BG1, emb);
    kMixPack<<<dim3(64,N_),256>>>(upd_w1, 128*64, OFF_WU1, emb);
    kMix<<<dim3(1,N_),256>>>(upd_b1, 64, OFF_BU1, emb);

    // ---- GRU layer 0 (C = 65) ----
    kZero<<<2456,256>>>(OFF_H, 32L*307*64);
    for (int t = 0; t < T_; t++) {
        kMM<1,128><<<dim3(17,5),256>>>(OFF_A,307, nullptr,0, OFF_SPR1,2080, nullptr,0,0,0, 307,307,2080,0, source,t);
        kGate<65,0><<<N_,256>>>(OFF_WG0, OFF_BG0, source, t);
        kMM<2,128><<<dim3(17,5),256>>>(OFF_A,307, nullptr,0, OFF_SPR2,2080, nullptr,0,0,0, 307,307,2080,0, source,t);
        kUpd<65,0><<<N_,256>>>(OFF_WU0, OFF_BU0, source, t, 1);
    }
    // ---- GRU layer 1 (C = 128) ----
    kZero<<<2456,256>>>(OFF_H, 32L*307*64);
    for (int t = 0; t < T_; t++) {
        kMM<3,128><<<dim3(32,5),256>>>(OFF_A,307, nullptr,0, OFF_SPR1,4096, nullptr,0,0,0, 307,307,4096,0, source,t);
        kGate<128,1><<<N_,256>>>(OFF_WG1, OFF_BG1, source, t);
        kMM<4,128><<<dim3(16,5),256>>>(OFF_A,307, nullptr,0, OFF_SPR2,2048, nullptr,0,0,0, 307,307,2048,0, source,t);
        kUpd<128,1><<<N_,256>>>(OFF_WU1, OFF_BU1, source, t, 0);
    }

    // ---- transformer branch (only t=11 survives) ----
    kX<<<29472,256>>>(source, mlp_w, mlp_b);
    kMM<0,64><<<dim3(1,1842),256>>>(OFF_XB,64, wk,64, OFF_K,64, bk, 0,0,0, 117888,64,64,0, nullptr,0);
    kMM<0,64><<<dim3(1,1842),256>>>(OFF_XB,64, wv,64, OFF_V,64, bv, 0,0,0, 117888,64,64,0, nullptr,0);
    kMM<0,64><<<dim3(1,154),256>>>(OFF_XB + 11*64,768, wq,64, OFF_Q,64, bq, 0,0,0, 9824,64,64,0, nullptr,0);
    kAttn<<<9824,128>>>();
    kMM<0,64><<<dim3(1,154),256>>>(OFF_OB,64, wo,64, OFF_Q,64, bo, OFF_XB + 11*64,768,1, 9824,64,64,0, nullptr,0);
    kLN<<<9824,64>>>(OFF_Q, OFF_LN1, l1g, l1b);
    kMM<0,128><<<dim3(8,154),256>>>(OFF_LN1,64, fw1,1024, OFF_F1,1024, fb1, 0,0,0, 9824,64,1024,1, nullptr,0);
    kMM<0,64><<<dim3(1,154),256>>>(OFF_F1,1024, fw2,64, OFF_F2,64, fb2, OFF_LN1,64,1, 9824,1024,64,0, nullptr,0);
    kLN<<<9824,64>>>(OFF_F2, OFF_OB, l2g, l2b);

    kOut<<<9824,64>>>(out, ws, wt, cw, cb);
}

// round 5
// speedup vs baseline: 1.3348x; 1.3130x over previous
#include <cuda_runtime.h>
#include <math.h>

#define N_ 307
#define T_ 12
#define B_ 32
#define H_ 64
#define E_ 10
#define NB 307

typedef unsigned long long ull;

constexpr long OFF_A     = 0;
constexpr long OFF_WG0   = OFF_A     + 94272;
constexpr long OFF_BG0   = OFF_WG0   + 307L*2*65*128;
constexpr long OFF_WU0   = OFF_BG0   + 307L*128;
constexpr long OFF_BU0   = OFF_WU0   + 307L*2*65*64;
constexpr long OFF_WG1   = OFF_BU0   + 307L*64;
constexpr long OFF_BG1   = OFF_WG1   + 307L*2*128*128;
constexpr long OFF_WU1   = OFF_BG1   + 307L*128;
constexpr long OFF_BU1   = OFF_WU1   + 307L*2*128*64;
constexpr long OFF_H     = OFF_BU1   + 307L*64;
constexpr long OFF_HS    = OFF_H     + 32L*307*64;
constexpr long OFF_AX    = OFF_HS    + 32L*12*307*64;
constexpr long OFF_AHS   = OFF_AX    + 307L*384;
constexpr long OFF_SPRH  = OFF_AHS   + 307L*24576;
constexpr long OFF_SPRZH = OFF_SPRH  + 307L*2048;
constexpr long OFF_ZR    = OFF_SPRZH + 307L*2048;
constexpr long OFF_XB    = OFF_ZR    + 307L*32*128;
constexpr long OFF_K     = OFF_XB    + 9824L*12*64;
constexpr long OFF_V     = OFF_K     + 9824L*12*64;
constexpr long OFF_Q     = OFF_V     + 9824L*12*64;
constexpr long OFF_OB    = OFF_Q     + 9824L*64;
constexpr long OFF_LN1   = OFF_OB    + 9824L*64;
constexpr long OFF_F1    = OFF_LN1   + 9824L*64;
constexpr long OFF_F2    = OFF_F1    + 9824L*1024;
constexpr long SCRATCH_TOTAL = OFF_F2 + 9824L*64;

__device__ float SCRATCH[SCRATCH_TOTAL];

// ---------------- grid barrier state ----------------
__device__ unsigned gCnt[8*32];   // one counter per 128B line
__device__ unsigned gMaster;
__device__ unsigned gGen;

__device__ __forceinline__ void gbar(unsigned &gen) {
    __syncthreads();
    if (threadIdx.x == 0) {
        __threadfence();
        int s = blockIdx.x & 7;
        unsigned quota = (s < 3) ? 39u : 38u;   // 307 = 8*38 + 3
        bool released = false;
        if (atomicAdd(&gCnt[s*32], 1) == quota - 1) {
            gCnt[s*32] = 0;
            if (atomicAdd(&gMaster, 1) == 7) {
                gMaster = 0;
                __threadfence();
                atomicAdd(&gGen, 1);
                released = true;
            }
        }
        if (!released) {
            while (atomicAdd(&gGen, 0) == gen) __nanosleep(64);
        }
        __threadfence();
    }
    __syncthreads();
    gen++;
}

// ---------------- host-side setup kernels ----------------
__global__ void kA(const float* __restrict__ emb) {
    int n = blockIdx.x, tid = threadIdx.x;
    __shared__ float sc[N_];
    __shared__ float red[256];
    __shared__ float en[E_];
    if (tid < E_) en[tid] = emb[n*E_ + tid];
    __syncthreads();
    for (int m = tid; m < N_; m += 256) {
        float s = 0.f;
        #pragma unroll
        for (int e = 0; e < E_; e++) s += en[e]*emb[m*E_+e];
        sc[m] = fmaxf(s, 0.f);
    }
    __syncthreads();
    float mx = -1e30f;
    for (int m = tid; m < N_; m += 256) mx = fmaxf(mx, sc[m]);
    red[tid] = mx; __syncthreads();
    for (int s = 128; s > 0; s >>= 1) { if (tid < s) red[tid] = fmaxf(red[tid], red[tid+s]); __syncthreads(); }
    mx = red[0]; __syncthreads();
    float sum = 0.f;
    for (int m = tid; m < N_; m += 256) { float e = expf(sc[m]-mx); sc[m] = e; sum += e; }
    red[tid] = sum; __syncthreads();
    for (int s = 128; s > 0; s >>= 1) { if (tid < s) red[tid] += red[tid+s]; __syncthreads(); }
    float inv = 1.f/red[0];
    __syncthreads();
    for (int m = tid; m < N_; m += 256) SCRATCH[OFF_A + (long)n*N_ + m] = sc[m]*inv;
}

__global__ void kMix(const float* __restrict__ w, int J, long dstOff, const float* __restrict__ emb) {
    int n = blockIdx.y;
    __shared__ float en[E_];
    if (threadIdx.x < E_) en[threadIdx.x] = emb[n*E_ + threadIdx.x];
    __syncthreads();
    int j = blockIdx.x*256 + threadIdx.x;
    if (j >= J) return;
    float a = 0.f;
    #pragma unroll
    for (int e = 0; e < E_; e++) a += en[e]*w[(long)e*J + j];
    SCRATCH[dstOff + (long)n*J + j] = a;
}

// packed weight mix: w[e][k][i][o] -> dst[n][(i*O+o)*2 + k]
__global__ void kMixPack(const float* __restrict__ w, int CO, long dstOff, const float* __restrict__ emb) {
    int n = blockIdx.y;
    __shared__ float en[E_];
    if (threadIdx.x < E_) en[threadIdx.x] = emb[n*E_ + threadIdx.x];
    __syncthreads();
    int j = blockIdx.x*256 + threadIdx.x;
    if (j >= 2*CO) return;
    float a = 0.f;
    #pragma unroll
    for (int e = 0; e < E_; e++) a += en[e]*w[(long)e*2*CO + j];
    int k = j / CO, r = j - k*CO;
    SCRATCH[dstOff + (long)n*2*CO + (long)r*2 + k] = a;
}

// ---------------- persistent GRU kernel pieces ----------------
// spread B-operand gather modes: 0 = A@x (all t), 1 = A@h, 2 = A@(z*h), 3 = A@hs (all t)
template<int MODE>
__device__ __forceinline__ float sprGather(const float* __restrict__ src, int m, int gc) {
    if (MODE == 0) {
        int tt = gc >> 5, b = gc & 31;
        return src[((long)b*T_ + tt)*N_ + m];
    }
    if (MODE == 1) {
        int b = gc >> 6, c = gc & 63;
        return SCRATCH[OFF_H + ((long)b*N_ + m)*H_ + c];
    }
    if (MODE == 2) {
        int b = gc >> 6, c = gc & 63;
        return SCRATCH[OFF_ZR + ((long)m*B_ + b)*128 + c] *
               SCRATCH[OFF_H + ((long)b*N_ + m)*H_ + c];
    }
    // MODE 3
    int tt = gc >> 11, b = (gc >> 6) & 31, c = gc & 63;
    return SCRATCH[OFF_HS + (((long)b*T_ + tt)*N_ + m)*H_ + c];
}

// 32x128-tile GEMM: out[0:307, 0:cols] = A(307x307) @ Bgather(307 x cols)
template<int MODE>
__device__ void dSpread(char* SMB, const float* __restrict__ src, long outOff, int cols) {
    float (*As)[16]  = (float(*)[16])SMB;            // 2 KB
    float (*Bs)[132] = (float(*)[132])(SMB + 2048);  // 8.25 KB
    int nColT = cols >> 7;
    int nT = 10 * nColT;
    int tx = threadIdx.x & 15, ty = threadIdx.x >> 4;
    for (int tile = blockIdx.x; tile < nT; tile += NB) {
        int tr = tile / nColT, tc = tile - tr*nColT;
        int row0 = tr*32, col0 = tc*128;
        ull acc[2][4];
        #pragma unroll
        for (int i=0;i<2;i++)
            #pragma unroll
            for (int p=0;p<4;p++) acc[i][p] = 0ull;
        for (int k0 = 0; k0 < N_; k0 += 16) {
            for (int e = threadIdx.x; e < 512; e += 256) {
                int r = e >> 4, c = e & 15, gr = row0 + r, gc = k0 + c;
                As[r][c] = (gr < N_ && gc < N_) ? SCRATCH[OFF_A + (long)gr*N_ + gc] : 0.f;
            }
            for (int e = threadIdx.x; e < 2048; e += 256) {
                int r = e >> 7, c = e & 127, m = k0 + r;
                Bs[r][c] = (m < N_) ? sprGather<MODE>(src, m, col0 + c) : 0.f;
            }
            __syncthreads();
            #pragma unroll
            for (int kk = 0; kk < 16; kk++) {
                ull b0 = *(const ull*)&Bs[kk][2*tx];
                ull b1 = *(const ull*)&Bs[kk][32 + 2*tx];
                ull b2 = *(const ull*)&Bs[kk][64 + 2*tx];
                ull b3 = *(const ull*)&Bs[kk][96 + 2*tx];
                #pragma unroll
                for (int i=0;i<2;i++) {
                    float a = As[ty + 16*i][kk];
                    ull aa;
                    asm("mov.b64 %0, {%1, %1};" : "=l"(aa) : "f"(a));
                    asm("fma.rn.f32x2 %0, %1, %2, %0;" : "+l"(acc[i][0]) : "l"(aa), "l"(b0));
                    asm("fma.rn.f32x2 %0, %1, %2, %0;" : "+l"(acc[i][1]) : "l"(aa), "l"(b1));
                    asm("fma.rn.f32x2 %0, %1, %2, %0;" : "+l"(acc[i][2]) : "l"(aa), "l"(b2));
                    asm("fma.rn.f32x2 %0, %1, %2, %0;" : "+l"(acc[i][3]) : "l"(aa), "l"(b3));
                }
            }
            __syncthreads();
        }
        #pragma unroll
        for (int i=0;i<2;i++) {
            int rr = row0 + ty + 16*i;
            if (rr >= N_) continue;
            #pragma unroll
            for (int p=0;p<4;p++)
                *(float2*)&SCRATCH[outOff + (long)rr*cols + col0 + 32*p + 2*tx] = *(float2*)&acc[i][p];
        }
    }
}

template<int C, int L>
__device__ void dGate(char* SMB, const float* __restrict__ src, int t, long wOff, long bOff) {
    int n = blockIdx.x, tid = threadIdx.x;
    float2* cs = (float2*)SMB;
    for (int idx = tid; idx < 32*C; idx += 256) {
        int b = idx / C, c = idx - b*C;
        float cv, sv;
        if (L == 0) {
            if (c == 0) { cv = src[((long)b*T_+t)*N_ + n]; sv = SCRATCH[OFF_AX + (long)n*384 + t*32 + b]; }
            else        { cv = SCRATCH[OFF_H + ((long)b*N_+n)*H_ + (c-1)];
                          sv = SCRATCH[OFF_SPRH + (long)n*2048 + b*64 + (c-1)]; }
        } else {
            if (c < 64) { cv = SCRATCH[OFF_HS + (((long)b*T_+t)*N_+n)*H_ + c];
                          sv = SCRATCH[OFF_AHS + (long)n*24576 + t*2048 + b*64 + c]; }
            else        { cv = SCRATCH[OFF_H + ((long)b*N_+n)*H_ + (c-64)];
                          sv = SCRATCH[OFF_SPRH + (long)n*2048 + b*64 + (c-64)]; }
        }
        cs[idx] = make_float2(cv, sv);
    }
    __syncthreads();
    int o = tid & 63, bg = tid >> 6;
    ull acc0[8], acc1[8];
    #pragma unroll
    for (int i=0;i<8;i++){acc0[i]=0ull;acc1[i]=0ull;}
    const float2* Wp = (const float2*)(SCRATCH + wOff + (long)n*(2*C*128));
    const float2* csb = cs + bg*8*C;
    #pragma unroll 2
    for (int i = 0; i < C; i++) {
        ull wa = *(const ull*)(Wp + i*128 + o);
        ull wb = *(const ull*)(Wp + i*128 + o + 64);
        #pragma unroll
        for (int bb = 0; bb < 8; bb++) {
            ull cp = *(const ull*)(csb + bb*C + i);
            asm("fma.rn.f32x2 %0, %1, %2, %0;" : "+l"(acc0[bb]) : "l"(cp), "l"(wa));
            asm("fma.rn.f32x2 %0, %1, %2, %0;" : "+l"(acc1[bb]) : "l"(cp), "l"(wb));
        }
    }
    float bias0 = SCRATCH[bOff + (long)n*128 + o];
    float bias1 = SCRATCH[bOff + (long)n*128 + o + 64];
    #pragma unroll
    for (int bb = 0; bb < 8; bb++) {
        float2 a0 = *(float2*)&acc0[bb];
        float2 a1 = *(float2*)&acc1[bb];
        long zi = OFF_ZR + ((long)n*32 + bg*8+bb)*128 + o;
        SCRATCH[zi]      = 1.f/(1.f + expf(-(a0.x + a0.y + bias0)));
        SCRATCH[zi + 64] = 1.f/(1.f + expf(-(a1.x + a1.y + bias1)));
    }
}

template<int C, int L>
__device__ void dUpd(char* SMB, const float* __restrict__ src, int t, long wOff, long bOff, int writeHS) {
    int n = blockIdx.x, tid = threadIdx.x;
    float2* cs = (float2*)SMB;
    for (int idx = tid; idx < 32*C; idx += 256) {
        int b = idx / C, c = idx - b*C;
        float cv, sv;
        if (L == 0) {
            if (c == 0) { cv = src[((long)b*T_+t)*N_ + n]; sv = SCRATCH[OFF_AX + (long)n*384 + t*32 + b]; }
            else {
                int j = c-1;
                cv = SCRATCH[OFF_ZR + ((long)n*32+b)*128 + j] * SCRATCH[OFF_H + ((long)b*N_+n)*H_ + j];
                sv = SCRATCH[OFF_SPRZH + (long)n*2048 + b*64 + j];
            }
        } else {
            if (c < 64) { cv = SCRATCH[OFF_HS + (((long)b*T_+t)*N_+n)*H_ + c];
                          sv = SCRATCH[OFF_AHS + (long)n*24576 + t*2048 + b*64 + c]; }
            else {
                int j = c-64;
                cv = SCRATCH[OFF_ZR + ((long)n*32+b)*128 + j] * SCRATCH[OFF_H + ((long)b*N_+n)*H_ + j];
                sv = SCRATCH[OFF_SPRZH + (long)n*2048 + b*64 + j];
            }
        }
        cs[idx] = make_float2(cv, sv);
    }
    __syncthreads();
    int o = tid & 31, bg = tid >> 5;
    ull acc0[4], acc1[4];
    #pragma unroll
    for (int i=0;i<4;i++){acc0[i]=0ull;acc1[i]=0ull;}
    const float2* Wp = (const float2*)(SCRATCH + wOff + (long)n*(2*C*64));
    const float2* csb = cs + bg*4*C;
    #pragma unroll 2
    for (int i = 0; i < C; i++) {
        ull wa = *(const ull*)(Wp + i*64 + o);
        ull wb = *(const ull*)(Wp + i*64 + o + 32);
        #pragma unroll
        for (int bb = 0; bb < 4; bb++) {
            ull cp = *(const ull*)(csb + bb*C + i);
            asm("fma.rn.f32x2 %0, %1, %2, %0;" : "+l"(acc0[bb]) : "l"(cp), "l"(wa));
            asm("fma.rn.f32x2 %0, %1, %2, %0;" : "+l"(acc1[bb]) : "l"(cp), "l"(wb));
        }
    }
    float bias0 = SCRATCH[bOff + (long)n*64 + o];
    float bias1 = SCRATCH[bOff + (long)n*64 + o + 32];
    #pragma unroll
    for (int bb = 0; bb < 4; bb++) {
        int b = bg*4 + bb;
        float2 a0 = *(float2*)&acc0[bb];
        float2 a1 = *(float2*)&acc1[bb];
        #pragma unroll
        for (int p = 0; p < 2; p++) {
            int oo = o + p*32;
            float hc = tanhf(p ? (a1.x+a1.y+bias1) : (a0.x+a0.y+bias0));
            float r  = SCRATCH[OFF_ZR + ((long)n*32 + b)*128 + 64 + oo];
            long hidx = OFF_H + ((long)b*N_ + n)*H_ + oo;
            float hn = r*SCRATCH[hidx] + (1.f - r)*hc;
            SCRATCH[hidx] = hn;
            if (writeHS) SCRATCH[OFF_HS + (((long)b*T_ + t)*N_ + n)*H_ + oo] = hn;
        }
    }
}

__device__ __forceinline__ void dZeroH() {
    for (long i = (long)blockIdx.x*256 + threadIdx.x; i < 32L*307*64; i += (long)NB*256)
        SCRATCH[OFF_H + i] = 0.f;
}

__global__ void __launch_bounds__(256, 4) kGRU(const float* __restrict__ src) {
    __shared__ __align__(16) char SMB[33280];
    unsigned gen = 0;
    if (threadIdx.x == 0) gen = atomicAdd(&gGen, 0);

    dSpread<0>(SMB, src, OFF_AX, 384);   // A @ x_t for all t
    dZeroH();
    gbar(gen);

    for (int t = 0; t < T_; t++) {       // layer 0
        dSpread<1>(SMB, src, OFF_SPRH, 2048);   gbar(gen);
        dGate<65,0>(SMB, src, t, OFF_WG0, OFF_BG0);  gbar(gen);
        dSpread<2>(SMB, src, OFF_SPRZH, 2048);  gbar(gen);
        dUpd<65,0>(SMB, src, t, OFF_WU0, OFF_BU0, 1); gbar(gen);
    }

    dSpread<3>(SMB, src, OFF_AHS, 24576); // A @ hs_t for all t
    dZeroH();
    gbar(gen);

    for (int t = 0; t < T_; t++) {       // layer 1
        dSpread<1>(SMB, src, OFF_SPRH, 2048);   gbar(gen);
        dGate<128,1>(SMB, src, t, OFF_WG1, OFF_BG1); gbar(gen);
        dSpread<2>(SMB, src, OFF_SPRZH, 2048);  gbar(gen);
        dUpd<128,1>(SMB, src, t, OFF_WU1, OFF_BU1, 0); gbar(gen);
    }
}

// ---------------- transformer branch (unchanged from R3) ----------------
template<int NT>
__global__ void __launch_bounds__(256) kMM(long aOff, int lda,
        const float* __restrict__ Bx, int ldb,
        long cOff, int ldc, const float* __restrict__ bias,
        long resOff, int ldres, int hasRes,
        int M, int K, int Nc, int relu) {
    const int P = NT/32;
    const float* A = SCRATCH + aOff;
    float* Cm = SCRATCH + cOff;
    __shared__ float As[64][16];
    __shared__ float Bs[16][NT+2];
    int tx = threadIdx.x & 15, ty = threadIdx.x >> 4;
    int row0 = blockIdx.y*64, col0 = blockIdx.x*NT;
    ull acc[4][P];
    #pragma unroll
    for (int i=0;i<4;i++)
        #pragma unroll
        for (int p=0;p<P;p++) acc[i][p] = 0ull;
    for (int k0 = 0; k0 < K; k0 += 16) {
        for (int e = threadIdx.x; e < 64*16; e += 256) {
            int r = e >> 4, c = e & 15, gr = row0 + r, gc = k0 + c;
            As[r][c] = (gr < M && gc < K) ? A[(long)gr*lda + gc] : 0.f;
        }
        for (int e = threadIdx.x; e < 16*NT; e += 256) {
            int r = e / NT, c = e - (e/NT)*NT;
            int gr = k0 + r, gc = col0 + c;
            Bs[r][c] = (gr < K && gc < Nc) ? Bx[(long)gr*ldb + gc] : 0.f;
        }
        __syncthreads();
        #pragma unroll
        for (int kk = 0; kk < 16; kk++) {
            ull bv[P];
            #pragma unroll
            for (int p=0;p<P;p++) bv[p] = *(const ull*)&Bs[kk][32*p + 2*tx];
            #pragma unroll
            for (int i=0;i<4;i++) {
                float a = As[ty + 16*i][kk];
                ull aa;
                asm("mov.b64 %0, {%1, %1};" : "=l"(aa) : "f"(a));
                #pragma unroll
                for (int p=0;p<P;p++)
                    asm("fma.rn.f32x2 %0, %1, %2, %0;" : "+l"(acc[i][p]) : "l"(aa), "l"(bv[p]));
            }
        }
        __syncthreads();
    }
    #pragma unroll
    for (int i=0;i<4;i++) {
        int rr = row0 + ty + 16*i;
        if (rr >= M) continue;
        #pragma unroll
        for (int p=0;p<P;p++) {
            float2 v = *(float2*)&acc[i][p];
            int cc = col0 + 32*p + 2*tx;
            #pragma unroll
            for (int q=0;q<2;q++) {
                int c2 = cc + q;
                if (c2 >= Nc) continue;
                float val = q ? v.y : v.x;
                if (bias)   val += bias[c2];
                if (hasRes) val += SCRATCH[resOff + (long)rr*ldres + c2];
                if (relu)   val = fmaxf(val, 0.f);
                Cm[(long)rr*ldc + c2] = val;
            }
        }
    }
}

__global__ void kX(const float* __restrict__ src, const float* __restrict__ mw,
                   const float* __restrict__ mb) {
    long idx = (long)blockIdx.x*256 + threadIdx.x;
    if (idx >= 9824L*12*64) return;
    int hh = (int)(idx & 63); long st = idx >> 6;
    int t = (int)(st % 12); long s = st / 12;
    int nn = (int)(s % N_); int b = (int)(s / N_);
    float j2 = (float)((hh >> 1)*2);
    float ang = (float)t * expf(-(j2/64.f)*9.210340371976184f);
    float pe = (hh & 1) ? cosf(ang) : sinf(ang);
    SCRATCH[OFF_XB + idx] = src[((long)b*T_ + t)*N_ + nn]*mw[hh] + mb[hh] + pe;
}

__global__ void kAttn() {
    int s = blockIdx.x, tid = threadIdx.x;
    int w = tid >> 5, lane = tid & 31;
    __shared__ float qs[64];
    __shared__ float att[4][12];
    if (tid < 64) qs[tid] = SCRATCH[OFF_Q + (long)s*64 + tid];
    __syncthreads();
    if (lane < 12) {
        float sc = 0.f;
        #pragma unroll
        for (int d = 0; d < 16; d++)
            sc += qs[w*16+d] * SCRATCH[OFF_K + (long)s*768 + lane*64 + w*16 + d];
        att[w][lane] = sc * 0.25f;
    }
    __syncwarp();
    float loc[12], mx = -1e30f, sum = 0.f;
    #pragma unroll
    for (int t = 0; t < 12; t++) { loc[t] = att[w][t]; mx = fmaxf(mx, loc[t]); }
    #pragma unroll
    for (int t = 0; t < 12; t++) { loc[t] = expf(loc[t]-mx); sum += loc[t]; }
    float inv = 1.f/sum;
    __syncwarp();
    if (lane < 16) {
        float acc = 0.f;
        #pragma unroll
        for (int t = 0; t < 12; t++)
            acc += loc[t]*inv * SCRATCH[OFF_V + (long)s*768 + t*64 + w*16 + lane];
        SCRATCH[OFF_OB + (long)s*64 + w*16 + lane] = acc;
    }
}

__global__ void kLN(long inOff, long outOff, const float* __restrict__ g, const float* __restrict__ b) {
    int row = blockIdx.x, tid = threadIdx.x;
    __shared__ float red[64];
    float v = SCRATCH[inOff + (long)row*64 + tid];
    red[tid] = v; __syncthreads();
    for (int s = 32; s > 0; s >>= 1) { if (tid < s) red[tid] += red[tid+s]; __syncthreads(); }
    float m = red[0]/64.f; __syncthreads();
    float d = v - m;
    red[tid] = d*d; __syncthreads();
    for (int s = 32; s > 0; s >>= 1) { if (tid < s) red[tid] += red[tid+s]; __syncthreads(); }
    float var = red[0]/64.f;
    SCRATCH[outOff + (long)row*64 + tid] = d*rsqrtf(var + 1e-5f)*g[tid] + b[tid];
}

__global__ void kOut(float* __restrict__ out, const float* __restrict__ ws, const float* __restrict__ wt,
                     const float* __restrict__ cw, const float* __restrict__ cb) {
    int s = blockIdx.x, tid = threadIdx.x;
    int n = s % N_, b = s / N_;
    __shared__ float comb[64];
    comb[tid] = SCRATCH[OFF_H + (long)s*64 + tid]*ws[n*64+tid]
              + SCRATCH[OFF_OB + (long)s*64 + tid]*wt[n*64+tid];
    __syncthreads();
    if (tid < 12) {
        float acc = cb[tid];
        #pragma unroll
        for (int h = 0; h < 64; h++) acc += comb[h]*cw[tid*64+h];
        out[((long)b*12 + tid)*N_ + n] = acc;
    }
}

extern "C" void kernel_launch(void* const* d_in, const int* in_sizes, int n_in,
                              void* d_out, int out_size) {
    const float* source  = (const float*)d_in[0];
    const float* emb     = (const float*)d_in[1];
    const float* gate_w0 = (const float*)d_in[2];
    const float* gate_b0 = (const float*)d_in[3];
    const float* upd_w0  = (const float*)d_in[4];
    const float* upd_b0  = (const float*)d_in[5];
    const float* gate_w1 = (const float*)d_in[6];
    const float* gate_b1 = (const float*)d_in[7];
    const float* upd_w1  = (const float*)d_in[8];
    const float* upd_b1  = (const float*)d_in[9];
    const float* mlp_w   = (const float*)d_in[10];
    const float* mlp_b   = (const float*)d_in[11];
    const float* wq = (const float*)d_in[12];  const float* bq = (const float*)d_in[13];
    const float* wk = (const float*)d_in[14];  const float* bk = (const float*)d_in[15];
    const float* wv = (const float*)d_in[16];  const float* bv = (const float*)d_in[17];
    const float* wo = (const float*)d_in[18];  const float* bo = (const float*)d_in[19];
    const float* fw1 = (const float*)d_in[20]; const float* fb1 = (const float*)d_in[21];
    const float* fw2 = (const float*)d_in[22]; const float* fb2 = (const float*)d_in[23];
    const float* l1g = (const float*)d_in[24]; const float* l1b = (const float*)d_in[25];
    const float* l2g = (const float*)d_in[26]; const float* l2b = (const float*)d_in[27];
    const float* ws  = (const float*)d_in[28]; const float* wt  = (const float*)d_in[29];
    const float* cw  = (const float*)d_in[30]; const float* cb  = (const float*)d_in[31];
    float* out = (float*)d_out;

    kA<<<N_, 256>>>(emb);
    kMixPack<<<dim3(65,N_),256>>>(gate_w0, 65*128, OFF_WG0, emb);
    kMix<<<dim3(1,N_),256>>>(gate_b0, 128, OFF_BG0, emb);
    kMixPack<<<dim3(33,N_),256>>>(upd_w0, 65*64, OFF_WU0, emb);
    kMix<<<dim3(1,N_),256>>>(upd_b0, 64, OFF_BU0, emb);
    kMixPack<<<dim3(128,N_),256>>>(gate_w1, 128*128, OFF_WG1, emb);
    kMix<<<dim3(1,N_),256>>>(gate_b1, 128, OFF_BG1, emb);
    kMixPack<<<dim3(64,N_),256>>>(upd_w1, 128*64, OFF_WU1, emb);
    kMix<<<dim3(1,N_),256>>>(upd_b1, 64, OFF_BU1, emb);

    kGRU<<<NB, 256>>>(source);

    kX<<<29472,256>>>(source, mlp_w, mlp_b);
    kMM<64><<<dim3(1,1842),256>>>(OFF_XB,64, wk,64, OFF_K,64, bk, 0,0,0, 117888,64,64,0);
    kMM<64><<<dim3(1,1842),256>>>(OFF_XB,64, wv,64, OFF_V,64, bv, 0,0,0, 117888,64,64,0);
    kMM<64><<<dim3(1,154),256>>>(OFF_XB + 11*64,768, wq,64, OFF_Q,64, bq, 0,0,0, 9824,64,64,0);
    kAttn<<<9824,128>>>();
    kMM<64><<<dim3(1,154),256>>>(OFF_OB,64, wo,64, OFF_Q,64, bo, OFF_XB + 11*64,768,1, 9824,64,64,0);
    kLN<<<9824,64>>>(OFF_Q, OFF_LN1, l1g, l1b);
    kMM<128><<<dim3(8,154),256>>>(OFF_LN1,64, fw1,1024, OFF_F1,1024, fb1, 0,0,0, 9824,64,1024,1);
    kMM<64><<<dim3(1,154),256>>>(OFF_F1,1024, fw2,64, OFF_F2,64, fb2, OFF_LN1,64,1, 9824,1024,64,0);
    kLN<<<9824,64>>>(OFF_F2, OFF_OB, l2g, l2b);

    kOut<<<9824,64>>>(out, ws, wt, cw, cb);
}